// round 8
// baseline (speedup 1.0000x reference)
#include <cuda_runtime.h>
#include <cuda_bf16.h>
#include <cstdint>

#define BB 256
#define TT 100
#define CC 40
#define H1 1024
#define H2 512
#define OO 35
#define MT (BB*TT)

// ---------------- static device scratch ----------------
__device__ __nv_bfloat162 g_P1h[(size_t)(MT + 4) * (H1/2)];  // (1-al1)-scaled drive, [b][t][pair], bf16x2
__device__ float g_xdT[(size_t)CC * MT];       // delayed input, transposed [c][r], r=b*TT+t
__device__ float g_WdT[CC * H1];               // (W_delay*sc1)^T : [c][h]
__device__ float g_shift1[H1];
__device__ float g_Wr1T[H1 * H1];              // [in][out] * sc1[out]*(1-al1[out])
__device__ float g_W2T [H1 * H2];              // [in][out] * sc2[out]*(1-al2[out])
__device__ float g_Wr2T[H2 * H2];              // [in][out] * sc2[out]*(1-al2[out])
__device__ float g_WoT [H2 * OO];              // [in][out] * (1-beta_out[out])

// ---------------- f32x2 packed helpers ----------------
__device__ __forceinline__ uint64_t pack2(float lo, float hi) {
    uint64_t r;
    asm("mov.b64 %0, {%1, %2};" : "=l"(r) : "r"(__float_as_uint(lo)), "r"(__float_as_uint(hi)));
    return r;
}
__device__ __forceinline__ uint64_t dup2(float v) {
    uint64_t r;
    asm("mov.b64 %0, {%1, %1};" : "=l"(r) : "r"(__float_as_uint(v)));
    return r;
}
__device__ __forceinline__ uint64_t fma2(uint64_t a, uint64_t b, uint64_t c) {
    uint64_t d;
    asm("fma.rn.f32x2 %0, %1, %2, %3;" : "=l"(d) : "l"(a), "l"(b), "l"(c));
    return d;
}
__device__ __forceinline__ uint64_t add2(uint64_t a, uint64_t b) {
    uint64_t d;
    asm("add.rn.f32x2 %0, %1, %2;" : "=l"(d) : "l"(a), "l"(b));
    return d;
}
__device__ __forceinline__ float2 unpack2(uint64_t v) {
    uint32_t lo, hi;
    asm("mov.b64 {%0, %1}, %2;" : "=r"(lo), "=r"(hi) : "l"(v));
    return make_float2(__uint_as_float(lo), __uint_as_float(hi));
}

// ---------------- prep: tiled transposes, scale folded (incl. (1-alpha)) --------------
__global__ void prep_kernel(const float* __restrict__ W_rec1,
                            const float* __restrict__ W2,
                            const float* __restrict__ W_rec2,
                            const float* __restrict__ W_out,
                            const float* __restrict__ W_delay,
                            const float* __restrict__ g1, const float* __restrict__ b1,
                            const float* __restrict__ m1, const float* __restrict__ v1,
                            const float* __restrict__ g2, const float* __restrict__ v2,
                            const float* __restrict__ alpha1, const float* __restrict__ alpha2,
                            const float* __restrict__ beta_out)
{
    __shared__ float tile[32][33];
    __shared__ float scs[32];
    const int z = blockIdx.z;
    const int tx = threadIdx.x, ty = threadIdx.y;   // (32, 8)

    if (z == 5) {
        if (blockIdx.y == 0) {
            int hh = blockIdx.x * 256 + ty * 32 + tx;
            if (hh < H1) {
                float sc = g1[hh] * rsqrtf(v1[hh] + 1e-5f);
                g_shift1[hh] = b1[hh] - m1[hh] * sc;
            }
        }
        return;
    }

    const float* src; float* dst;
    int R, Cc;                       // src is [R rows(o)][Cc cols(h)]
    if      (z == 0) { src = W_rec1;  dst = g_Wr1T; R = H1; Cc = H1; }
    else if (z == 1) { src = W2;      dst = g_W2T;  R = H2; Cc = H1; }
    else if (z == 2) { src = W_rec2;  dst = g_Wr2T; R = H2; Cc = H2; }
    else if (z == 3) { src = W_out;   dst = g_WoT;  R = OO; Cc = H2; }
    else             { src = W_delay; dst = g_WdT;  R = H1; Cc = CC; }

    const int x0 = blockIdx.x * 32;  // over cols h
    const int y0 = blockIdx.y * 32;  // over rows o
    if (x0 >= Cc || y0 >= R) return;

    if (ty == 0) {
        int o = y0 + tx;
        float sc = 1.0f;
        if (o < R) {
            if (z == 0)                 sc = g1[o] * rsqrtf(v1[o] + 1e-5f) * (1.0f - alpha1[o]);
            else if (z == 1 || z == 2)  sc = g2[o] * rsqrtf(v2[o] + 1e-5f) * (1.0f - alpha2[o]);
            else if (z == 3)            sc = 1.0f - beta_out[o];
            else                        sc = g1[o] * rsqrtf(v1[o] + 1e-5f);
        }
        scs[tx] = sc;
    }
    __syncthreads();

    #pragma unroll
    for (int k = 0; k < 4; k++) {
        int o = y0 + ty + 8*k;
        int hh = x0 + tx;
        if (o < R && hh < Cc)
            tile[ty + 8*k][tx] = src[(size_t)o * Cc + hh] * scs[ty + 8*k];
    }
    __syncthreads();
    #pragma unroll
    for (int k = 0; k < 4; k++) {
        int hh = x0 + ty + 8*k;
        int o = y0 + tx;
        if (hh < Cc && o < R) dst[(size_t)hh * R + o] = tile[tx][ty + 8*k];
    }
}

// ---------------- xd: delayed-input gather, transposed output [c][b*TT+t] -------------
__global__ __launch_bounds__(256) void xd_kernel(const float* __restrict__ x,
                                                 const float* __restrict__ delay_raw)
{
    __shared__ float sx[TT * CC];
    __shared__ int   fli[CC];
    __shared__ float frac[CC];

    const int b   = blockIdx.x;
    const int tid = threadIdx.x;

    if (tid < CC) {
        float xr = delay_raw[tid];
        float s  = (xr >= 0.0f) ? (1.0f / (1.0f + expf(-xr)))
                                : (expf(xr) / (1.0f + expf(xr)));
        float d  = s * 30.0f;        // MAX_DELAY
        float fl = floorf(d);
        fli[tid]  = (int)fl;
        frac[tid] = d - fl;
    }
    const float* xb = x + (size_t)b * TT * CC;
    for (int i = tid; i < TT * CC; i += 256) sx[i] = xb[i];
    __syncthreads();

    for (int i = tid; i < TT * CC; i += 256) {
        int c = i / TT, t = i - c * TT;
        int i0 = t - fli[c];
        float fr = frac[c];
        float x0 = (i0 >= 0) ? sx[i0 * CC + c]       : 0.0f;
        float x1 = (i0 >= 1) ? sx[(i0 - 1) * CC + c] : 0.0f;
        g_xdT[(size_t)c * MT + b * TT + t] = (1.0f - fr) * x0 + fr * x1;
    }
}

// ---------------- P1 GEMM: 128x128, f32x2 mainloop, bf16x2 packed stores --------------
__global__ __launch_bounds__(256) void gemm_p1_kernel(const float* __restrict__ alpha1)
{
    __shared__ __align__(16) float xs[CC][128];
    __shared__ __align__(16) float ws[CC][128];
    __shared__ float sh1s[128];
    __shared__ float omas[128];

    const int tid = threadIdx.x;
    const int h0  = blockIdx.x * 128;
    const int r0  = blockIdx.y * 128;

    #pragma unroll
    for (int v = tid; v < 32 * CC; v += 256) {
        int c = v >> 5, off = v & 31;
        ((float4*)xs)[c * 32 + off] = ((const float4*)(g_xdT + (size_t)c * MT + r0))[off];
    }
    #pragma unroll
    for (int v = tid; v < 32 * CC; v += 256) {
        int c = v >> 5, off = v & 31;
        ((float4*)ws)[c * 32 + off] = ((const float4*)(g_WdT + c * H1 + h0))[off];
    }
    if (tid < 128) {
        sh1s[tid] = g_shift1[h0 + tid];
        omas[tid] = 1.0f - alpha1[h0 + tid];
    }
    __syncthreads();

    const int ty = tid >> 4;
    const int tx = tid & 15;

    uint64_t acc[8][4];
    #pragma unroll
    for (int i = 0; i < 8; i++)
        #pragma unroll
        for (int j = 0; j < 4; j++) acc[i][j] = 0ULL;

    #pragma unroll
    for (int k = 0; k < CC; k++) {
        float4 A0 = *(const float4*)&xs[k][ty * 8];
        float4 A1 = *(const float4*)&xs[k][ty * 8 + 4];
        float4 W0 = *(const float4*)&ws[k][tx * 8];
        float4 W1 = *(const float4*)&ws[k][tx * 8 + 4];
        uint64_t w01 = pack2(W0.x, W0.y);
        uint64_t w23 = pack2(W0.z, W0.w);
        uint64_t w45 = pack2(W1.x, W1.y);
        uint64_t w67 = pack2(W1.z, W1.w);
        float av[8] = {A0.x, A0.y, A0.z, A0.w, A1.x, A1.y, A1.z, A1.w};
        #pragma unroll
        for (int ii = 0; ii < 8; ii++) {
            uint64_t ad = dup2(av[ii]);
            acc[ii][0] = fma2(ad, w01, acc[ii][0]);
            acc[ii][1] = fma2(ad, w23, acc[ii][1]);
            acc[ii][2] = fma2(ad, w45, acc[ii][2]);
            acc[ii][3] = fma2(ad, w67, acc[ii][3]);
        }
    }

    uint64_t sh0 = pack2(sh1s[tx*8+0], sh1s[tx*8+1]);
    uint64_t sh1 = pack2(sh1s[tx*8+2], sh1s[tx*8+3]);
    uint64_t sh2 = pack2(sh1s[tx*8+4], sh1s[tx*8+5]);
    uint64_t sh3 = pack2(sh1s[tx*8+6], sh1s[tx*8+7]);
    float om[8];
    #pragma unroll
    for (int j = 0; j < 8; j++) om[j] = omas[tx*8+j];

    #pragma unroll
    for (int ii = 0; ii < 8; ii++) {
        int r = r0 + ty * 8 + ii;
        float2 p0 = unpack2(add2(acc[ii][0], sh0));
        float2 p1 = unpack2(add2(acc[ii][1], sh1));
        float2 p2 = unpack2(add2(acc[ii][2], sh2));
        float2 p3 = unpack2(add2(acc[ii][3], sh3));
        __nv_bfloat162 b0 = __float22bfloat162_rn(make_float2(p0.x*om[0], p0.y*om[1]));
        __nv_bfloat162 b1 = __float22bfloat162_rn(make_float2(p1.x*om[2], p1.y*om[3]));
        __nv_bfloat162 b2 = __float22bfloat162_rn(make_float2(p2.x*om[4], p2.y*om[5]));
        __nv_bfloat162 b3 = __float22bfloat162_rn(make_float2(p3.x*om[6], p3.y*om[7]));
        uint4 pk;
        pk.x = *(uint32_t*)&b0; pk.y = *(uint32_t*)&b1;
        pk.z = *(uint32_t*)&b2; pk.w = *(uint32_t*)&b3;
        *(uint4*)&g_P1h[(size_t)r * (H1/2) + (h0 + tx * 8) / 2] = pk;
    }
}

// ---------------- step kernel: 256 CTAs x 128 thr; 8 L1 + 4 L2 neurons per thread ------
// Spike exchange via bitmaps + any-flags; zero-spike fast path skips all gathers.
// Triple-buffered; 1 __syncthreads per step (schedule identical to R6 proven version).

#define L1_UPD(i, PCV)                                                                     \
{                                                                                          \
    float s = (s1bits & (1u << (i))) ? 1.0f : 0.0f;                                        \
    float an = rh1r[i] * a1r[i] + ba1r[i] * s;                                             \
    float vn = al1r[i] * v1r[i] + (PCV) + r##i - an - s;                                   \
    a1r[i] = an; v1r[i] = vn;                                                              \
    if (vn >= 1.0f) nb1 |= (1u << (i));                                                    \
}

#define L2_UPD(i, UV)                                                                      \
{                                                                                          \
    float s = (s2bits & (1u << (i))) ? 1.0f : 0.0f;                                        \
    float an = rh2r[i] * a2r[i] + ba2r[i] * s;                                             \
    float vn = al2r[i] * v2r[i] + (UV) - an - s;                                           \
    a2r[i] = an; v2r[i] = vn;                                                              \
    if (vn >= 1.0f) nb2 |= (1u << (i));                                                    \
}

#define SNN_STEP(RQ1, WQ1, ZQ1, DO_L1, DO_RO)                                              \
{                                                                                          \
    /* zero free buffers (not read or written this step) */                               \
    if (tid < 32)       s_m1[ZQ1][tid] = 0u;                                               \
    else if (tid < 48)  s_m2[WQ1][tid - 32] = 0u;                                          \
    else if (tid == 48) s_any1[ZQ1] = 0;                                                   \
    else if (tid == 49) s_any2[WQ1] = 0;                                                   \
    /* ---- L2(t): reads s1(t)=m1[RQ1], s2(t-1)=m2[ZQ1]; writes s2(t)->m2[RQ1] ---- */     \
    {                                                                                      \
        float u0 = sh2r[0], u1 = sh2r[1], u2 = sh2r[2], u3 = sh2r[3];                      \
        if (s_any1[RQ1]) {                                                                 \
            for (int w = 0; w < 32; w++) { unsigned m = s_m1[RQ1][w];                      \
                while (m) { int j = __ffs(m) - 1; m &= m - 1;                              \
                    float4 ww = *(const float4*)(g_W2T + (w*32 + j) * H2 + 4*tid);         \
                    u0 += ww.x; u1 += ww.y; u2 += ww.z; u3 += ww.w; } }                    \
        }                                                                                  \
        if (s_any2[ZQ1]) {                                                                 \
            for (int w = 0; w < 16; w++) { unsigned m = s_m2[ZQ1][w];                      \
                while (m) { int j = __ffs(m) - 1; m &= m - 1;                              \
                    float4 ww = *(const float4*)(g_Wr2T + (w*32 + j) * H2 + 4*tid);        \
                    u0 += ww.x; u1 += ww.y; u2 += ww.z; u3 += ww.w; } }                    \
        }                                                                                  \
        unsigned nb2 = 0u;                                                                 \
        L2_UPD(0, u0) L2_UPD(1, u1) L2_UPD(2, u2) L2_UPD(3, u3)                            \
        s2bits = nb2;                                                                      \
        if (nb2) { atomicOr((int*)&s_m2[RQ1][tid >> 3], (int)(nb2 << (4*(tid & 7))));      \
                   s_any2[RQ1] = 1; }                                                      \
    }                                                                                      \
    /* ---- L1(t+1): reads s1(t)=m1[RQ1], P1(t+1); writes m1[WQ1] ---- */                  \
    if (DO_L1) {                                                                           \
        float r0=0.f,r1=0.f,r2=0.f,r3=0.f,r4=0.f,r5=0.f,r6=0.f,r7=0.f;                     \
        if (s_any1[RQ1]) {                                                                 \
            for (int w = 0; w < 32; w++) { unsigned m = s_m1[RQ1][w];                      \
                while (m) { int j = __ffs(m) - 1; m &= m - 1;                              \
                    const float* row = g_Wr1T + (size_t)(w*32 + j) * H1 + 8*tid;           \
                    float4 wa = *(const float4*)row;                                       \
                    float4 wb = *(const float4*)(row + 4);                                 \
                    r0 += wa.x; r1 += wa.y; r2 += wa.z; r3 += wa.w;                        \
                    r4 += wb.x; r5 += wb.y; r6 += wb.z; r7 += wb.w; } }                    \
        }                                                                                  \
        float2 f0 = __bfloat1622float2(*(const __nv_bfloat162*)&p1.x);                     \
        float2 f1 = __bfloat1622float2(*(const __nv_bfloat162*)&p1.y);                     \
        float2 f2 = __bfloat1622float2(*(const __nv_bfloat162*)&p1.z);                     \
        float2 f3 = __bfloat1622float2(*(const __nv_bfloat162*)&p1.w);                     \
        unsigned nb1 = 0u;                                                                 \
        L1_UPD(0, f0.x) L1_UPD(1, f0.y) L1_UPD(2, f1.x) L1_UPD(3, f1.y)                    \
        L1_UPD(4, f2.x) L1_UPD(5, f2.y) L1_UPD(6, f3.x) L1_UPD(7, f3.y)                    \
        s1bits = nb1;                                                                      \
        if (nb1) { atomicOr((int*)&s_m1[WQ1][tid >> 2], (int)(nb1 << (8*(tid & 3))));      \
                   s_any1[WQ1] = 1; }                                                      \
    }                                                                                      \
    /* ---- readout(t-1): reads s2(t-1)=m2[ZQ1] ---- */                                    \
    if (DO_RO && tid < OO) {                                                               \
        float io = 0.f;                                                                    \
        if (s_any2[ZQ1]) {                                                                 \
            for (int w = 0; w < 16; w++) { unsigned m = s_m2[ZQ1][w];                      \
                while (m) { int j = __ffs(m) - 1; m &= m - 1;                              \
                    io += g_WoT[(w*32 + j) * OO + tid]; } }                                \
        }                                                                                  \
        vo = bo * vo + io; accv += vo;                                                     \
    }                                                                                      \
    { uint4 q = *pfu; pfu += 128;                                                          \
      __syncthreads();                                                                     \
      p1 = p2; p2 = q; }                                                                   \
}

__global__ __launch_bounds__(128) void snn_kernel(
    const float* __restrict__ bn2_gamma, const float* __restrict__ bn2_beta,
    const float* __restrict__ bn2_mean,  const float* __restrict__ bn2_var,
    const float* __restrict__ alpha1, const float* __restrict__ rho1, const float* __restrict__ beta_a1,
    const float* __restrict__ alpha2, const float* __restrict__ rho2, const float* __restrict__ beta_a2,
    const float* __restrict__ beta_out,
    float* __restrict__ out)
{
    __shared__ unsigned s_m1[3][32];   // L1 spike bitmaps (1024 bits)
    __shared__ unsigned s_m2[3][16];   // L2 spike bitmaps (512 bits)
    __shared__ int s_any1[3], s_any2[3];

    const int tid = threadIdx.x;
    const int b   = blockIdx.x;

    for (int i = tid; i < 3*32; i += 128) ((unsigned*)s_m1)[i] = 0u;
    if (tid < 3*16) ((unsigned*)s_m2)[tid] = 0u;
    if (tid < 3) { s_any1[tid] = 0; s_any2[tid] = 0; }

    // ---- L1: neurons [8*tid, 8*tid+8) ----
    float al1r[8], rh1r[8], ba1r[8], v1r[8], a1r[8];
    {
        float4 a0 = *(const float4*)(alpha1  + 8*tid), a1_ = *(const float4*)(alpha1  + 8*tid + 4);
        float4 b0 = *(const float4*)(rho1    + 8*tid), b1_ = *(const float4*)(rho1    + 8*tid + 4);
        float4 c0 = *(const float4*)(beta_a1 + 8*tid), c1_ = *(const float4*)(beta_a1 + 8*tid + 4);
        al1r[0]=a0.x; al1r[1]=a0.y; al1r[2]=a0.z; al1r[3]=a0.w;
        al1r[4]=a1_.x; al1r[5]=a1_.y; al1r[6]=a1_.z; al1r[7]=a1_.w;
        rh1r[0]=b0.x; rh1r[1]=b0.y; rh1r[2]=b0.z; rh1r[3]=b0.w;
        rh1r[4]=b1_.x; rh1r[5]=b1_.y; rh1r[6]=b1_.z; rh1r[7]=b1_.w;
        ba1r[0]=c0.x; ba1r[1]=c0.y; ba1r[2]=c0.z; ba1r[3]=c0.w;
        ba1r[4]=c1_.x; ba1r[5]=c1_.y; ba1r[6]=c1_.z; ba1r[7]=c1_.w;
        #pragma unroll
        for (int i = 0; i < 8; i++) { v1r[i] = 0.f; a1r[i] = 0.f; }
    }
    unsigned s1bits = 0u;

    // ---- L2: neurons [4*tid, 4*tid+4) ----
    float al2r[4], rh2r[4], ba2r[4], sh2r[4], v2r[4], a2r[4];
    {
        float4 g = *(const float4*)(bn2_gamma + 4*tid);
        float4 vv = *(const float4*)(bn2_var  + 4*tid);
        float4 be = *(const float4*)(bn2_beta + 4*tid);
        float4 me = *(const float4*)(bn2_mean + 4*tid);
        float4 a  = *(const float4*)(alpha2   + 4*tid);
        float4 r  = *(const float4*)(rho2     + 4*tid);
        float4 c  = *(const float4*)(beta_a2  + 4*tid);
        float gg[4] = {g.x,g.y,g.z,g.w}, vvv[4] = {vv.x,vv.y,vv.z,vv.w};
        float bb[4] = {be.x,be.y,be.z,be.w}, mm[4] = {me.x,me.y,me.z,me.w};
        float aa[4] = {a.x,a.y,a.z,a.w}, rr[4] = {r.x,r.y,r.z,r.w}, cc[4] = {c.x,c.y,c.z,c.w};
        #pragma unroll
        for (int i = 0; i < 4; i++) {
            float sc = gg[i] * rsqrtf(vvv[i] + 1e-5f);
            al2r[i] = aa[i]; rh2r[i] = rr[i]; ba2r[i] = cc[i];
            sh2r[i] = (1.0f - aa[i]) * (bb[i] - mm[i] * sc);
            v2r[i] = 0.f; a2r[i] = 0.f;
        }
    }
    unsigned s2bits = 0u;

    // ---- readout ----
    float vo = 0.f, accv = 0.f, bo = 0.f;
    if (tid < OO) bo = beta_out[tid];

    // ---- P1 pipeline: one uint4 (= 8 bf16) per thread per step ----
    const uint4* baseu = (const uint4*)(g_P1h + (size_t)b * TT * (H1/2)) + tid;
    uint4 p0 = baseu[0];
    uint4 p1 = baseu[128];
    uint4 p2 = baseu[256];
    const uint4* pfu = baseu + 384;

    __syncthreads();

    // ---- prologue: L1(0) -> m1[0] ----
    {
        float2 f0 = __bfloat1622float2(*(const __nv_bfloat162*)&p0.x);
        float2 f1 = __bfloat1622float2(*(const __nv_bfloat162*)&p0.y);
        float2 f2 = __bfloat1622float2(*(const __nv_bfloat162*)&p0.z);
        float2 f3 = __bfloat1622float2(*(const __nv_bfloat162*)&p0.w);
        float r0=0,r1=0,r2=0,r3=0,r4=0,r5=0,r6=0,r7=0;
        (void)r0;(void)r1;(void)r2;(void)r3;(void)r4;(void)r5;(void)r6;(void)r7;
        unsigned nb1 = 0u;
        L1_UPD(0, f0.x) L1_UPD(1, f0.y) L1_UPD(2, f1.x) L1_UPD(3, f1.y)
        L1_UPD(4, f2.x) L1_UPD(5, f2.y) L1_UPD(6, f3.x) L1_UPD(7, f3.y)
        s1bits = nb1;
        if (nb1) { atomicOr((int*)&s_m1[0][tid >> 2], (int)(nb1 << (8*(tid & 3))));
                   s_any1[0] = 1; }
    }
    __syncthreads();

    // iter t=0 (no readout), then 32 triples t=1..96, then t=97,98,99
    SNN_STEP(0, 1, 2, 1, 0)
    #pragma unroll 1
    for (int k = 0; k < 32; k++) {
        SNN_STEP(1, 2, 0, 1, 1)
        SNN_STEP(2, 0, 1, 1, 1)
        SNN_STEP(0, 1, 2, 1, 1)
    }
    SNN_STEP(1, 2, 0, 1, 1)     // t=97
    SNN_STEP(2, 0, 1, 1, 1)     // t=98
    SNN_STEP(0, 1, 2, 0, 1)     // t=99, no L1(100)

    // ---- epilogue: readout(99): s2(99) in m2[0] ----
    if (tid < OO) {
        float io = 0.f;
        if (s_any2[0]) {
            for (int w = 0; w < 16; w++) { unsigned m = s_m2[0][w];
                while (m) { int j = __ffs(m) - 1; m &= m - 1;
                    io += g_WoT[(w*32 + j) * OO + tid]; } }
        }
        vo = bo * vo + io;
        accv += vo;
        out[b * OO + tid] = accv * (1.0f / (float)TT);
    }
}

// ---------------- launch ----------------
extern "C" void kernel_launch(void* const* d_in, const int* in_sizes, int n_in,
                              void* d_out, int out_size)
{
    const float* x         = (const float*)d_in[0];
    const float* W_delay   = (const float*)d_in[1];
    const float* delay_raw = (const float*)d_in[2];
    const float* W_rec1    = (const float*)d_in[3];
    const float* W2        = (const float*)d_in[4];
    const float* W_rec2    = (const float*)d_in[5];
    const float* W_out     = (const float*)d_in[6];
    const float* bn1_gamma = (const float*)d_in[7];
    const float* bn1_beta  = (const float*)d_in[8];
    const float* bn1_mean  = (const float*)d_in[9];
    const float* bn1_var   = (const float*)d_in[10];
    const float* bn2_gamma = (const float*)d_in[11];
    const float* bn2_beta  = (const float*)d_in[12];
    const float* bn2_mean  = (const float*)d_in[13];
    const float* bn2_var   = (const float*)d_in[14];
    const float* alpha1    = (const float*)d_in[15];
    const float* rho1      = (const float*)d_in[16];
    const float* beta_a1   = (const float*)d_in[17];
    const float* alpha2    = (const float*)d_in[18];
    const float* rho2      = (const float*)d_in[19];
    const float* beta_a2   = (const float*)d_in[20];
    const float* beta_out  = (const float*)d_in[21];

    dim3 pb(32, 8);
    dim3 pg(32, 32, 6);
    prep_kernel<<<pg, pb>>>(W_rec1, W2, W_rec2, W_out, W_delay,
                            bn1_gamma, bn1_beta, bn1_mean, bn1_var,
                            bn2_gamma, bn2_var,
                            alpha1, alpha2, beta_out);

    xd_kernel<<<BB, 256>>>(x, delay_raw);

    dim3 gg(H1 / 128, MT / 128);   // (8, 200)
    gemm_p1_kernel<<<gg, 256>>>(alpha1);

    snn_kernel<<<BB, 128>>>(bn2_gamma, bn2_beta, bn2_mean, bn2_var,
                            alpha1, rho1, beta_a1,
                            alpha2, rho2, beta_a2,
                            beta_out,
                            (float*)d_out);
}

// round 9
// speedup vs baseline: 1.2039x; 1.2039x over previous
#include <cuda_runtime.h>
#include <cstdint>

#define BB 256
#define TT 100
#define CC 40
#define H1 1024
#define H2 512
#define OO 35

typedef unsigned long long u64;

// ---------------- global flags/results ----------------
__device__ int   g_flag[BB];     // 1 if batch b had any L1 spike (needs full sim)
__device__ float g_quiet[OO];    // readout trajectory accumulator for the quiet case

// ---------------- f32x2 packed helpers ----------------
__device__ __forceinline__ u64 pack2(float lo, float hi) {
    u64 r;
    asm("mov.b64 %0, {%1, %2};" : "=l"(r) : "r"(__float_as_uint(lo)), "r"(__float_as_uint(hi)));
    return r;
}
__device__ __forceinline__ u64 fma2(u64 a, u64 b, u64 c) {
    u64 d;
    asm("fma.rn.f32x2 %0, %1, %2, %3;" : "=l"(d) : "l"(a), "l"(b), "l"(c));
    return d;
}
__device__ __forceinline__ u64 add2(u64 a, u64 b) {
    u64 d;
    asm("add.rn.f32x2 %0, %1, %2;" : "=l"(d) : "l"(a), "l"(b));
    return d;
}
__device__ __forceinline__ float2 unpack2(u64 v) {
    uint32_t lo, hi;
    asm("mov.b64 {%0, %1}, %2;" : "=r"(lo), "=r"(hi) : "l"(v));
    return make_float2(__uint_as_float(lo), __uint_as_float(hi));
}

__device__ __forceinline__ float sigmoidf_(float xr) {
    return (xr >= 0.0f) ? (1.0f / (1.0f + expf(-xr)))
                        : (expf(xr) / (1.0f + expf(xr)));
}

// =======================================================================================
// Kernel 1: barrier-free speculative L1 scan (CTAs 0..255) + quiet L2 sim (CTA 256).
// =======================================================================================
__global__ __launch_bounds__(512, 1) void scan_kernel(
    const float* __restrict__ x,
    const float* __restrict__ delay_raw,
    const float* __restrict__ W_delay,
    const float* __restrict__ bn1_gamma, const float* __restrict__ bn1_beta,
    const float* __restrict__ bn1_mean,  const float* __restrict__ bn1_var,
    const float* __restrict__ alpha1, const float* __restrict__ rho1, const float* __restrict__ beta_a1,
    const float* __restrict__ bn2_gamma, const float* __restrict__ bn2_beta,
    const float* __restrict__ bn2_mean,  const float* __restrict__ bn2_var,
    const float* __restrict__ alpha2, const float* __restrict__ rho2, const float* __restrict__ beta_a2,
    const float* __restrict__ W_rec2, const float* __restrict__ W_out,
    const float* __restrict__ beta_out)
{
    const int tid = threadIdx.x;

    // ---------------- CTA 256: quiet (batch-independent) L2 + readout simulation -------
    if (blockIdx.x == BB) {
        __shared__ int qlist[2][H2];
        __shared__ int qcnt[2];
        if (tid < 2) qcnt[tid] = 0;

        const float sc2 = bn2_gamma[tid] * rsqrtf(bn2_var[tid] + 1e-5f);
        const float al2 = alpha2[tid];
        const float om2 = 1.0f - al2;
        const float sh2 = om2 * (bn2_beta[tid] - bn2_mean[tid] * sc2);
        const float scom = sc2 * om2;
        const float rh2 = rho2[tid], ba2 = beta_a2[tid];
        float v2 = 0.f, a2 = 0.f, s2 = 0.f;

        float vo = 0.f, acc = 0.f, bo = 0.f, obo = 0.f;
        if (tid < OO) { bo = beta_out[tid]; obo = 1.0f - bo; }
        __syncthreads();

        for (int t = 0; t < TT; t++) {
            const int q = t & 1, p = q ^ 1;
            float u = sh2;
            int n = qcnt[p];
            if (n) {
                float su = 0.f;
                for (int j = 0; j < n; j++) su += W_rec2[(size_t)tid * H2 + qlist[p][j]];
                u += scom * su;
            }
            float an = rh2 * a2 + ba2 * s2;
            float vn = al2 * v2 + u - an - s2;
            float sn = (vn >= 1.0f) ? 1.0f : 0.0f;
            a2 = an; v2 = vn; s2 = sn;
            if (sn != 0.0f) { int pos = atomicAdd(&qcnt[q], 1); qlist[q][pos] = tid; }
            __syncthreads();
            if (tid < OO) {
                float io = 0.f;
                int m = qcnt[q];
                for (int j = 0; j < m; j++) io += W_out[(size_t)tid * H2 + qlist[q][j]];
                vo = bo * vo + obo * io;
                acc += vo;
            }
            if (tid == 0) qcnt[p] = 0;
            __syncthreads();
        }
        if (tid < OO) g_quiet[tid] = acc * (1.0f / (float)TT);
        return;
    }

    // ---------------- CTAs 0..255: speculative barrier-free L1 scan for batch b --------
    __shared__ u64  xdd[TT][CC];    // delayed input, each value duplicated {v,v} (32 KB)
    __shared__ int   fli[CC];
    __shared__ float frac[CC];

    const int b = blockIdx.x;

    if (tid < CC) {
        float d  = sigmoidf_(delay_raw[tid]) * 30.0f;   // MAX_DELAY
        float fl = floorf(d);
        fli[tid]  = (int)fl;
        frac[tid] = d - fl;
    }
    __syncthreads();

    // fill delayed-input table (duplicated for direct f32x2 consumption)
    {
        const float* xb = x + (size_t)b * TT * CC;
        for (int i = tid; i < TT * CC; i += 512) {
            int t = i / CC, c = i - t * CC;
            int i0 = t - fli[c];
            float fr = frac[c];
            float x0 = (i0 >= 0) ? xb[i0 * CC + c]       : 0.0f;
            float x1 = (i0 >= 1) ? xb[(i0 - 1) * CC + c] : 0.0f;
            float v = (1.0f - fr) * x0 + fr * x1;
            xdd[t][c] = pack2(v, v);
        }
    }

    // per-thread neuron pair (h0 = 2*tid, h1 = 2*tid+1), weights folded with sc1*(1-al1)
    const int h0 = 2 * tid, h1 = 2 * tid + 1;
    const float sc10 = bn1_gamma[h0] * rsqrtf(bn1_var[h0] + 1e-5f);
    const float sc11 = bn1_gamma[h1] * rsqrtf(bn1_var[h1] + 1e-5f);
    const float al0 = alpha1[h0], al1v = alpha1[h1];
    const float om0 = 1.0f - al0, om1 = 1.0f - al1v;
    const float shc0 = om0 * (bn1_beta[h0] - bn1_mean[h0] * sc10);
    const float shc1 = om1 * (bn1_beta[h1] - bn1_mean[h1] * sc11);
    const float rh0 = rho1[h0], rh1v = rho1[h1];
    const float ba0 = beta_a1[h0], ba1v = beta_a1[h1];
    const float f0 = sc10 * om0, f1 = sc11 * om1;

    u64 Wp[CC];
    #pragma unroll
    for (int c = 0; c < CC; c++)
        Wp[c] = pack2(W_delay[h0 * CC + c] * f0, W_delay[h1 * CC + c] * f1);

    float v0 = 0.f, a0 = 0.f, s0 = 0.f;
    float v1 = 0.f, a1 = 0.f, s1 = 0.f;
    int spiked = 0;

    __syncthreads();   // xdd ready

    #pragma unroll 1
    for (int t = 0; t < TT; t++) {
        const ulonglong2* row = (const ulonglong2*)&xdd[t][0];
        u64 acc0 = pack2(shc0, shc1);
        u64 acc1 = 0ULL;
        #pragma unroll
        for (int k = 0; k < CC / 2; k++) {
            ulonglong2 q = row[k];              // LDS.128 broadcast: xd[c], xd[c+1]
            acc0 = fma2(Wp[2 * k],     q.x, acc0);
            acc1 = fma2(Wp[2 * k + 1], q.y, acc1);
        }
        float2 I = unpack2(add2(acc0, acc1));

        float an0 = rh0 * a0 + ba0 * s0;
        float vn0 = al0 * v0 + I.x - an0 - s0;
        float an1 = rh1v * a1 + ba1v * s1;
        float vn1 = al1v * v1 + I.y - an1 - s1;
        s0 = (vn0 >= 1.0f) ? 1.0f : 0.0f;
        s1 = (vn1 >= 1.0f) ? 1.0f : 0.0f;
        spiked |= (s0 != 0.0f) | (s1 != 0.0f);
        a0 = an0; v0 = vn0;
        a1 = an1; v1 = vn1;
    }

    int any = __syncthreads_or(spiked);
    if (tid == 0) g_flag[b] = any;
}

// =======================================================================================
// Kernel 2: finalize. Quiet batches broadcast g_quiet; flagged batches get a full,
// correct (slow-path) re-simulation with spike lists.
// =======================================================================================
__global__ __launch_bounds__(512, 1) void finalize_kernel(
    const float* __restrict__ x,
    const float* __restrict__ delay_raw,
    const float* __restrict__ W_delay,
    const float* __restrict__ bn1_gamma, const float* __restrict__ bn1_beta,
    const float* __restrict__ bn1_mean,  const float* __restrict__ bn1_var,
    const float* __restrict__ alpha1, const float* __restrict__ rho1, const float* __restrict__ beta_a1,
    const float* __restrict__ bn2_gamma, const float* __restrict__ bn2_beta,
    const float* __restrict__ bn2_mean,  const float* __restrict__ bn2_var,
    const float* __restrict__ alpha2, const float* __restrict__ rho2, const float* __restrict__ beta_a2,
    const float* __restrict__ W_rec1, const float* __restrict__ W2,
    const float* __restrict__ W_rec2, const float* __restrict__ W_out,
    const float* __restrict__ beta_out,
    float* __restrict__ out)
{
    const int tid = threadIdx.x;
    const int b   = blockIdx.x;

    if (g_flag[b] == 0) {
        if (tid < OO) out[b * OO + tid] = g_quiet[tid];
        return;
    }

    // ------------------ full correct simulation of batch b (rare path) -----------------
    __shared__ float xd[TT][CC];
    __shared__ int   fli[CC];
    __shared__ float frac[CC];
    __shared__ int l1[2][H1], l2[2][H2];
    __shared__ int c1[2], c2[2];

    if (tid < CC) {
        float d  = sigmoidf_(delay_raw[tid]) * 30.0f;
        float fl = floorf(d);
        fli[tid]  = (int)fl;
        frac[tid] = d - fl;
    }
    if (tid < 2) { c1[tid] = 0; c2[tid] = 0; }
    __syncthreads();

    {
        const float* xb = x + (size_t)b * TT * CC;
        for (int i = tid; i < TT * CC; i += 512) {
            int t = i / CC, c = i - t * CC;
            int i0 = t - fli[c];
            float fr = frac[c];
            float x0 = (i0 >= 0) ? xb[i0 * CC + c]       : 0.0f;
            float x1 = (i0 >= 1) ? xb[(i0 - 1) * CC + c] : 0.0f;
            xd[t][c] = (1.0f - fr) * x0 + fr * x1;
        }
    }

    // L1: neurons h0 = tid, h1 = tid + 512
    const int h0 = tid, h1 = tid + 512;
    const float sc10 = bn1_gamma[h0] * rsqrtf(bn1_var[h0] + 1e-5f);
    const float sc11 = bn1_gamma[h1] * rsqrtf(bn1_var[h1] + 1e-5f);
    const float al10 = alpha1[h0], al11 = alpha1[h1];
    const float om10 = 1.0f - al10, om11 = 1.0f - al11;
    const float shc0 = om10 * (bn1_beta[h0] - bn1_mean[h0] * sc10);
    const float shc1 = om11 * (bn1_beta[h1] - bn1_mean[h1] * sc11);
    const float sf0 = sc10 * om10, sf1 = sc11 * om11;
    const float rh10 = rho1[h0], rh11 = rho1[h1];
    const float ba10 = beta_a1[h0], ba11 = beta_a1[h1];
    float Wd0[CC], Wd1[CC];
    #pragma unroll
    for (int c = 0; c < CC; c++) { Wd0[c] = W_delay[h0 * CC + c]; Wd1[c] = W_delay[h1 * CC + c]; }
    float v10 = 0.f, a10 = 0.f, s10 = 0.f;
    float v11 = 0.f, a11 = 0.f, s11 = 0.f;

    // L2: neuron tid
    const float sc2 = bn2_gamma[tid] * rsqrtf(bn2_var[tid] + 1e-5f);
    const float al2 = alpha2[tid];
    const float om2 = 1.0f - al2;
    const float sh2 = om2 * (bn2_beta[tid] - bn2_mean[tid] * sc2);
    const float scom = sc2 * om2;
    const float rh2 = rho2[tid], ba2 = beta_a2[tid];
    float v2 = 0.f, a2 = 0.f, s2 = 0.f;

    float vo = 0.f, acc = 0.f, bo = 0.f, obo = 0.f;
    if (tid < OO) { bo = beta_out[tid]; obo = 1.0f - bo; }

    __syncthreads();

    for (int t = 0; t < TT; t++) {
        const int q = t & 1, p = q ^ 1;

        // ---- L1(t): reads s1(t-1) spikes in l1[p] ----
        float d0 = 0.f, d1 = 0.f;
        #pragma unroll
        for (int c = 0; c < CC; c++) { float xv = xd[t][c]; d0 += Wd0[c] * xv; d1 += Wd1[c] * xv; }
        float r0 = 0.f, r1 = 0.f;
        {
            int n = c1[p];
            for (int j = 0; j < n; j++) {
                int jj = l1[p][j];
                r0 += W_rec1[(size_t)h0 * H1 + jj];
                r1 += W_rec1[(size_t)h1 * H1 + jj];
            }
        }
        {
            float I  = sf0 * (d0 + r0) + shc0;
            float an = rh10 * a10 + ba10 * s10;
            float vn = al10 * v10 + I - an - s10;
            float sn = (vn >= 1.0f) ? 1.0f : 0.0f;
            a10 = an; v10 = vn; s10 = sn;
            if (sn != 0.0f) { int pos = atomicAdd(&c1[q], 1); l1[q][pos] = h0; }
        }
        {
            float I  = sf1 * (d1 + r1) + shc1;
            float an = rh11 * a11 + ba11 * s11;
            float vn = al11 * v11 + I - an - s11;
            float sn = (vn >= 1.0f) ? 1.0f : 0.0f;
            a11 = an; v11 = vn; s11 = sn;
            if (sn != 0.0f) { int pos = atomicAdd(&c1[q], 1); l1[q][pos] = h1; }
        }
        __syncthreads();

        // ---- L2(t): reads s1(t) in l1[q] and s2(t-1) in l2[p] ----
        {
            float su = 0.f;
            int m = c1[q];
            for (int j = 0; j < m; j++) su += W2[(size_t)tid * H1 + l1[q][j]];
            int m2 = c2[p];
            for (int j = 0; j < m2; j++) su += W_rec2[(size_t)tid * H2 + l2[p][j]];
            float u  = sh2 + scom * su;
            float an = rh2 * a2 + ba2 * s2;
            float vn = al2 * v2 + u - an - s2;
            float sn = (vn >= 1.0f) ? 1.0f : 0.0f;
            a2 = an; v2 = vn; s2 = sn;
            if (sn != 0.0f) { int pos = atomicAdd(&c2[q], 1); l2[q][pos] = tid; }
        }
        __syncthreads();

        // ---- readout(t): reads s2(t) in l2[q] ----
        if (tid < OO) {
            float io = 0.f;
            int m = c2[q];
            for (int j = 0; j < m; j++) io += W_out[(size_t)tid * H2 + l2[q][j]];
            vo = bo * vo + obo * io;
            acc += vo;
        }
        if (tid == 0) { c1[p] = 0; c2[p] = 0; }
        __syncthreads();
    }

    if (tid < OO) out[b * OO + tid] = acc * (1.0f / (float)TT);
}

// ---------------- launch ----------------
extern "C" void kernel_launch(void* const* d_in, const int* in_sizes, int n_in,
                              void* d_out, int out_size)
{
    const float* x         = (const float*)d_in[0];
    const float* W_delay   = (const float*)d_in[1];
    const float* delay_raw = (const float*)d_in[2];
    const float* W_rec1    = (const float*)d_in[3];
    const float* W2        = (const float*)d_in[4];
    const float* W_rec2    = (const float*)d_in[5];
    const float* W_out     = (const float*)d_in[6];
    const float* bn1_gamma = (const float*)d_in[7];
    const float* bn1_beta  = (const float*)d_in[8];
    const float* bn1_mean  = (const float*)d_in[9];
    const float* bn1_var   = (const float*)d_in[10];
    const float* bn2_gamma = (const float*)d_in[11];
    const float* bn2_beta  = (const float*)d_in[12];
    const float* bn2_mean  = (const float*)d_in[13];
    const float* bn2_var   = (const float*)d_in[14];
    const float* alpha1    = (const float*)d_in[15];
    const float* rho1      = (const float*)d_in[16];
    const float* beta_a1   = (const float*)d_in[17];
    const float* alpha2    = (const float*)d_in[18];
    const float* rho2      = (const float*)d_in[19];
    const float* beta_a2   = (const float*)d_in[20];
    const float* beta_out  = (const float*)d_in[21];

    scan_kernel<<<BB + 1, 512>>>(x, delay_raw, W_delay,
                                 bn1_gamma, bn1_beta, bn1_mean, bn1_var,
                                 alpha1, rho1, beta_a1,
                                 bn2_gamma, bn2_beta, bn2_mean, bn2_var,
                                 alpha2, rho2, beta_a2,
                                 W_rec2, W_out, beta_out);

    finalize_kernel<<<BB, 512>>>(x, delay_raw, W_delay,
                                 bn1_gamma, bn1_beta, bn1_mean, bn1_var,
                                 alpha1, rho1, beta_a1,
                                 bn2_gamma, bn2_beta, bn2_mean, bn2_var,
                                 alpha2, rho2, beta_a2,
                                 W_rec1, W2, W_rec2, W_out, beta_out,
                                 (float*)d_out);
}

// round 10
// speedup vs baseline: 1.4026x; 1.1650x over previous
#include <cuda_runtime.h>
#include <cuda_bf16.h>
#include <cstdint>

#define BB 256
#define TT 100
#define CC 40
#define H1 1024
#define H2 512
#define OO 35
#define MT (BB*TT)

typedef unsigned long long u64;

// ---------------- static device scratch ----------------
__device__ __nv_bfloat162 g_P1h[(size_t)(MT + 4) * (H1/2)];  // (1-al1)-scaled drive, [b][t][pair]
__device__ float g_xdT[(size_t)CC * MT];    // delayed input, transposed [c][r], r=b*TT+t
__device__ float g_WdT[CC * H1];            // (W_delay*sc1)^T : [c][h]
__device__ float g_shift1[H1];
__device__ int   g_flag[BB];                // 1 if batch b had any L1 spike
__device__ float g_quiet[OO];               // quiet-case readout accumulator

// ---------------- f32x2 packed helpers ----------------
__device__ __forceinline__ u64 pack2(float lo, float hi) {
    u64 r;
    asm("mov.b64 %0, {%1, %2};" : "=l"(r) : "r"(__float_as_uint(lo)), "r"(__float_as_uint(hi)));
    return r;
}
__device__ __forceinline__ u64 dup2(float v) {
    u64 r;
    asm("mov.b64 %0, {%1, %1};" : "=l"(r) : "r"(__float_as_uint(v)));
    return r;
}
__device__ __forceinline__ u64 fma2(u64 a, u64 b, u64 c) {
    u64 d;
    asm("fma.rn.f32x2 %0, %1, %2, %3;" : "=l"(d) : "l"(a), "l"(b), "l"(c));
    return d;
}
__device__ __forceinline__ u64 add2(u64 a, u64 b) {
    u64 d;
    asm("add.rn.f32x2 %0, %1, %2;" : "=l"(d) : "l"(a), "l"(b));
    return d;
}
__device__ __forceinline__ float2 unpack2(u64 v) {
    uint32_t lo, hi;
    asm("mov.b64 {%0, %1}, %2;" : "=r"(lo), "=r"(hi) : "l"(v));
    return make_float2(__uint_as_float(lo), __uint_as_float(hi));
}
__device__ __forceinline__ float sigmoidf_(float xr) {
    return (xr >= 0.0f) ? (1.0f / (1.0f + expf(-xr)))
                        : (expf(xr) / (1.0f + expf(xr)));
}

// ---------------- prep (slim): WdT = (W_delay * sc1)^T, shift1 -------------------------
__global__ void prep_kernel(const float* __restrict__ W_delay,
                            const float* __restrict__ g1, const float* __restrict__ b1,
                            const float* __restrict__ m1, const float* __restrict__ v1)
{
    int i = blockIdx.x * blockDim.x + threadIdx.x;
    if (i < CC * H1) {
        int c = i >> 10, h = i & (H1 - 1);
        float sc = g1[h] * rsqrtf(v1[h] + 1e-5f);
        g_WdT[i] = W_delay[h * CC + c] * sc;
    }
    if (i < H1) {
        float sc = g1[i] * rsqrtf(v1[i] + 1e-5f);
        g_shift1[i] = b1[i] - m1[i] * sc;
    }
}

// ---------------- xd: delayed-input gather, transposed output [c][b*TT+t] -------------
__global__ __launch_bounds__(256) void xd_kernel(const float* __restrict__ x,
                                                 const float* __restrict__ delay_raw)
{
    __shared__ float sx[TT * CC];
    __shared__ int   fli[CC];
    __shared__ float frac[CC];

    const int b   = blockIdx.x;
    const int tid = threadIdx.x;

    if (tid < CC) {
        float d  = sigmoidf_(delay_raw[tid]) * 30.0f;    // MAX_DELAY
        float fl = floorf(d);
        fli[tid]  = (int)fl;
        frac[tid] = d - fl;
    }
    const float* xb = x + (size_t)b * TT * CC;
    for (int i = tid; i < TT * CC; i += 256) sx[i] = xb[i];
    __syncthreads();

    for (int i = tid; i < TT * CC; i += 256) {
        int c = i / TT, t = i - c * TT;
        int i0 = t - fli[c];
        float fr = frac[c];
        float x0 = (i0 >= 0) ? sx[i0 * CC + c]       : 0.0f;
        float x1 = (i0 >= 1) ? sx[(i0 - 1) * CC + c] : 0.0f;
        g_xdT[(size_t)c * MT + b * TT + t] = (1.0f - fr) * x0 + fr * x1;
    }
}

// ---------------- P1 GEMM: 128x128, f32x2 mainloop, bf16x2 packed stores --------------
__global__ __launch_bounds__(256) void gemm_p1_kernel(const float* __restrict__ alpha1)
{
    __shared__ __align__(16) float xs[CC][128];
    __shared__ __align__(16) float ws[CC][128];
    __shared__ float sh1s[128];
    __shared__ float omas[128];

    const int tid = threadIdx.x;
    const int h0  = blockIdx.x * 128;
    const int r0  = blockIdx.y * 128;

    #pragma unroll
    for (int v = tid; v < 32 * CC; v += 256) {
        int c = v >> 5, off = v & 31;
        ((float4*)xs)[c * 32 + off] = ((const float4*)(g_xdT + (size_t)c * MT + r0))[off];
    }
    #pragma unroll
    for (int v = tid; v < 32 * CC; v += 256) {
        int c = v >> 5, off = v & 31;
        ((float4*)ws)[c * 32 + off] = ((const float4*)(g_WdT + c * H1 + h0))[off];
    }
    if (tid < 128) {
        sh1s[tid] = g_shift1[h0 + tid];
        omas[tid] = 1.0f - alpha1[h0 + tid];
    }
    __syncthreads();

    const int ty = tid >> 4;
    const int tx = tid & 15;

    u64 acc[8][4];
    #pragma unroll
    for (int i = 0; i < 8; i++)
        #pragma unroll
        for (int j = 0; j < 4; j++) acc[i][j] = 0ULL;

    #pragma unroll
    for (int k = 0; k < CC; k++) {
        float4 A0 = *(const float4*)&xs[k][ty * 8];
        float4 A1 = *(const float4*)&xs[k][ty * 8 + 4];
        float4 W0 = *(const float4*)&ws[k][tx * 8];
        float4 W1 = *(const float4*)&ws[k][tx * 8 + 4];
        u64 w01 = pack2(W0.x, W0.y);
        u64 w23 = pack2(W0.z, W0.w);
        u64 w45 = pack2(W1.x, W1.y);
        u64 w67 = pack2(W1.z, W1.w);
        float av[8] = {A0.x, A0.y, A0.z, A0.w, A1.x, A1.y, A1.z, A1.w};
        #pragma unroll
        for (int ii = 0; ii < 8; ii++) {
            u64 ad = dup2(av[ii]);
            acc[ii][0] = fma2(ad, w01, acc[ii][0]);
            acc[ii][1] = fma2(ad, w23, acc[ii][1]);
            acc[ii][2] = fma2(ad, w45, acc[ii][2]);
            acc[ii][3] = fma2(ad, w67, acc[ii][3]);
        }
    }

    u64 sh0 = pack2(sh1s[tx*8+0], sh1s[tx*8+1]);
    u64 sh1 = pack2(sh1s[tx*8+2], sh1s[tx*8+3]);
    u64 sh2 = pack2(sh1s[tx*8+4], sh1s[tx*8+5]);
    u64 sh3 = pack2(sh1s[tx*8+6], sh1s[tx*8+7]);
    float om[8];
    #pragma unroll
    for (int j = 0; j < 8; j++) om[j] = omas[tx*8+j];

    #pragma unroll
    for (int ii = 0; ii < 8; ii++) {
        int r = r0 + ty * 8 + ii;
        float2 p0 = unpack2(add2(acc[ii][0], sh0));
        float2 p1 = unpack2(add2(acc[ii][1], sh1));
        float2 p2 = unpack2(add2(acc[ii][2], sh2));
        float2 p3 = unpack2(add2(acc[ii][3], sh3));
        __nv_bfloat162 b0 = __float22bfloat162_rn(make_float2(p0.x*om[0], p0.y*om[1]));
        __nv_bfloat162 b1 = __float22bfloat162_rn(make_float2(p1.x*om[2], p1.y*om[3]));
        __nv_bfloat162 b2 = __float22bfloat162_rn(make_float2(p2.x*om[4], p2.y*om[5]));
        __nv_bfloat162 b3 = __float22bfloat162_rn(make_float2(p3.x*om[6], p3.y*om[7]));
        uint4 pk;
        pk.x = *(uint32_t*)&b0; pk.y = *(uint32_t*)&b1;
        pk.z = *(uint32_t*)&b2; pk.w = *(uint32_t*)&b3;
        *(uint4*)&g_P1h[(size_t)r * (H1/2) + (h0 + tx * 8) / 2] = pk;
    }
}

// =======================================================================================
// spec_scan: barrier-free per-(batch, neuron-pair) adLIF scan over bf16 P1 (blocks 0..255)
//            + quiet (batch-independent) L2/readout simulation (block 256).
// =======================================================================================
__global__ __launch_bounds__(512) void spec_scan_kernel(
    const float* __restrict__ alpha1, const float* __restrict__ rho1, const float* __restrict__ beta_a1,
    const float* __restrict__ bn2_gamma, const float* __restrict__ bn2_beta,
    const float* __restrict__ bn2_mean,  const float* __restrict__ bn2_var,
    const float* __restrict__ alpha2, const float* __restrict__ rho2, const float* __restrict__ beta_a2,
    const float* __restrict__ W_rec2, const float* __restrict__ W_out,
    const float* __restrict__ beta_out)
{
    const int tid = threadIdx.x;

    if (blockIdx.x == BB) {
        // ---------------- quiet L2 + readout simulation (exact fp32) ----
        __shared__ int qlist[2][H2];
        __shared__ int qcnt[2];
        if (tid < 2) qcnt[tid] = 0;

        const float sc2 = bn2_gamma[tid] * rsqrtf(bn2_var[tid] + 1e-5f);
        const float al2 = alpha2[tid];
        const float om2 = 1.0f - al2;
        const float sh2 = om2 * (bn2_beta[tid] - bn2_mean[tid] * sc2);
        const float scom = sc2 * om2;
        const float rh2 = rho2[tid], ba2 = beta_a2[tid];
        float v2 = 0.f, a2 = 0.f, s2 = 0.f;

        float vo = 0.f, acc = 0.f, bo = 0.f, obo = 0.f;
        if (tid < OO) { bo = beta_out[tid]; obo = 1.0f - bo; }
        __syncthreads();

        for (int t = 0; t < TT; t++) {
            const int q = t & 1, p = q ^ 1;
            float u = sh2;
            int n = qcnt[p];
            if (n) {
                float su = 0.f;
                for (int j = 0; j < n; j++) su += W_rec2[(size_t)tid * H2 + qlist[p][j]];
                u += scom * su;
            }
            float an = rh2 * a2 + ba2 * s2;
            float vn = al2 * v2 + u - an - s2;
            float sn = (vn >= 1.0f) ? 1.0f : 0.0f;
            a2 = an; v2 = vn; s2 = sn;
            if (sn != 0.0f) { int pos = atomicAdd(&qcnt[q], 1); qlist[q][pos] = tid; }
            __syncthreads();
            if (tid < OO) {
                float io = 0.f;
                int m = qcnt[q];
                for (int j = 0; j < m; j++) io += W_out[(size_t)tid * H2 + qlist[q][j]];
                vo = bo * vo + obo * io;
                acc += vo;
            }
            if (tid == 0) qcnt[p] = 0;
            __syncthreads();
        }
        if (tid < OO) g_quiet[tid] = acc * (1.0f / (float)TT);
        return;
    }

    // ---------------- blocks 0..255: batch b, thread owns neuron pair (2*tid, 2*tid+1) --
    const int b = blockIdx.x;

    const float2 AL = *(const float2*)(alpha1  + 2 * tid);
    const float2 RH = *(const float2*)(rho1    + 2 * tid);
    const float2 BA = *(const float2*)(beta_a1 + 2 * tid);

    float v0 = 0.f, a0 = 0.f, s0 = 0.f;
    float v1 = 0.f, a1 = 0.f, s1 = 0.f;
    int spiked = 0;

    const uint32_t* p = (const uint32_t*)g_P1h + (size_t)b * TT * (H1/2) + tid;

    #pragma unroll 4
    for (int t = 0; t < TT; t++) {
        uint32_t pk = *p; p += (H1/2);
        float2 pc = __bfloat1622float2(*(const __nv_bfloat162*)&pk);

        float an0 = RH.x * a0 + BA.x * s0;
        float vn0 = AL.x * v0 + pc.x - an0 - s0;
        float an1 = RH.y * a1 + BA.y * s1;
        float vn1 = AL.y * v1 + pc.y - an1 - s1;
        s0 = (vn0 >= 1.0f) ? 1.0f : 0.0f;
        s1 = (vn1 >= 1.0f) ? 1.0f : 0.0f;
        spiked |= (s0 != 0.0f) | (s1 != 0.0f);
        a0 = an0; v0 = vn0;
        a1 = an1; v1 = vn1;
    }

    int any = __syncthreads_or(spiked);
    if (tid == 0) g_flag[b] = any;
}

// =======================================================================================
// finalize: quiet batches broadcast g_quiet; flagged batches get a full exact re-sim.
// =======================================================================================
__global__ __launch_bounds__(512, 1) void finalize_kernel(
    const float* __restrict__ x,
    const float* __restrict__ delay_raw,
    const float* __restrict__ W_delay,
    const float* __restrict__ bn1_gamma, const float* __restrict__ bn1_beta,
    const float* __restrict__ bn1_mean,  const float* __restrict__ bn1_var,
    const float* __restrict__ alpha1, const float* __restrict__ rho1, const float* __restrict__ beta_a1,
    const float* __restrict__ bn2_gamma, const float* __restrict__ bn2_beta,
    const float* __restrict__ bn2_mean,  const float* __restrict__ bn2_var,
    const float* __restrict__ alpha2, const float* __restrict__ rho2, const float* __restrict__ beta_a2,
    const float* __restrict__ W_rec1, const float* __restrict__ W2,
    const float* __restrict__ W_rec2, const float* __restrict__ W_out,
    const float* __restrict__ beta_out,
    float* __restrict__ out)
{
    const int tid = threadIdx.x;
    const int b   = blockIdx.x;

    if (g_flag[b] == 0) {
        if (tid < OO) out[b * OO + tid] = g_quiet[tid];
        return;
    }

    // ------------------ full correct simulation of batch b (rare path) -----------------
    __shared__ float xd[TT][CC];
    __shared__ int   fli[CC];
    __shared__ float frac[CC];
    __shared__ int l1[2][H1], l2[2][H2];
    __shared__ int c1[2], c2[2];

    if (tid < CC) {
        float d  = sigmoidf_(delay_raw[tid]) * 30.0f;
        float fl = floorf(d);
        fli[tid]  = (int)fl;
        frac[tid] = d - fl;
    }
    if (tid < 2) { c1[tid] = 0; c2[tid] = 0; }
    __syncthreads();

    {
        const float* xb = x + (size_t)b * TT * CC;
        for (int i = tid; i < TT * CC; i += 512) {
            int t = i / CC, c = i - t * CC;
            int i0 = t - fli[c];
            float fr = frac[c];
            float x0 = (i0 >= 0) ? xb[i0 * CC + c]       : 0.0f;
            float x1 = (i0 >= 1) ? xb[(i0 - 1) * CC + c] : 0.0f;
            xd[t][c] = (1.0f - fr) * x0 + fr * x1;
        }
    }

    const int h0 = tid, h1 = tid + 512;
    const float sc10 = bn1_gamma[h0] * rsqrtf(bn1_var[h0] + 1e-5f);
    const float sc11 = bn1_gamma[h1] * rsqrtf(bn1_var[h1] + 1e-5f);
    const float al10 = alpha1[h0], al11 = alpha1[h1];
    const float om10 = 1.0f - al10, om11 = 1.0f - al11;
    const float shc0 = om10 * (bn1_beta[h0] - bn1_mean[h0] * sc10);
    const float shc1 = om11 * (bn1_beta[h1] - bn1_mean[h1] * sc11);
    const float sf0 = sc10 * om10, sf1 = sc11 * om11;
    const float rh10 = rho1[h0], rh11 = rho1[h1];
    const float ba10 = beta_a1[h0], ba11 = beta_a1[h1];
    float Wd0[CC], Wd1[CC];
    #pragma unroll
    for (int c = 0; c < CC; c++) { Wd0[c] = W_delay[h0 * CC + c]; Wd1[c] = W_delay[h1 * CC + c]; }
    float v10 = 0.f, a10 = 0.f, s10 = 0.f;
    float v11 = 0.f, a11 = 0.f, s11 = 0.f;

    const float sc2 = bn2_gamma[tid] * rsqrtf(bn2_var[tid] + 1e-5f);
    const float al2 = alpha2[tid];
    const float om2 = 1.0f - al2;
    const float sh2 = om2 * (bn2_beta[tid] - bn2_mean[tid] * sc2);
    const float scom = sc2 * om2;
    const float rh2 = rho2[tid], ba2 = beta_a2[tid];
    float v2 = 0.f, a2 = 0.f, s2 = 0.f;

    float vo = 0.f, acc = 0.f, bo = 0.f, obo = 0.f;
    if (tid < OO) { bo = beta_out[tid]; obo = 1.0f - bo; }

    __syncthreads();

    for (int t = 0; t < TT; t++) {
        const int q = t & 1, p = q ^ 1;

        float d0 = 0.f, d1 = 0.f;
        #pragma unroll
        for (int c = 0; c < CC; c++) { float xv = xd[t][c]; d0 += Wd0[c] * xv; d1 += Wd1[c] * xv; }
        float r0 = 0.f, r1 = 0.f;
        {
            int n = c1[p];
            for (int j = 0; j < n; j++) {
                int jj = l1[p][j];
                r0 += W_rec1[(size_t)h0 * H1 + jj];
                r1 += W_rec1[(size_t)h1 * H1 + jj];
            }
        }
        {
            float I  = sf0 * (d0 + r0) + shc0;
            float an = rh10 * a10 + ba10 * s10;
            float vn = al10 * v10 + I - an - s10;
            float sn = (vn >= 1.0f) ? 1.0f : 0.0f;
            a10 = an; v10 = vn; s10 = sn;
            if (sn != 0.0f) { int pos = atomicAdd(&c1[q], 1); l1[q][pos] = h0; }
        }
        {
            float I  = sf1 * (d1 + r1) + shc1;
            float an = rh11 * a11 + ba11 * s11;
            float vn = al11 * v11 + I - an - s11;
            float sn = (vn >= 1.0f) ? 1.0f : 0.0f;
            a11 = an; v11 = vn; s11 = sn;
            if (sn != 0.0f) { int pos = atomicAdd(&c1[q], 1); l1[q][pos] = h1; }
        }
        __syncthreads();

        {
            float su = 0.f;
            int m = c1[q];
            for (int j = 0; j < m; j++) su += W2[(size_t)tid * H1 + l1[q][j]];
            int m2 = c2[p];
            for (int j = 0; j < m2; j++) su += W_rec2[(size_t)tid * H2 + l2[p][j]];
            float u  = sh2 + scom * su;
            float an = rh2 * a2 + ba2 * s2;
            float vn = al2 * v2 + u - an - s2;
            float sn = (vn >= 1.0f) ? 1.0f : 0.0f;
            a2 = an; v2 = vn; s2 = sn;
            if (sn != 0.0f) { int pos = atomicAdd(&c2[q], 1); l2[q][pos] = tid; }
        }
        __syncthreads();

        if (tid < OO) {
            float io = 0.f;
            int m = c2[q];
            for (int j = 0; j < m; j++) io += W_out[(size_t)tid * H2 + l2[q][j]];
            vo = bo * vo + obo * io;
            acc += vo;
        }
        if (tid == 0) { c1[p] = 0; c2[p] = 0; }
        __syncthreads();
    }

    if (tid < OO) out[b * OO + tid] = acc * (1.0f / (float)TT);
}

// ---------------- launch ----------------
extern "C" void kernel_launch(void* const* d_in, const int* in_sizes, int n_in,
                              void* d_out, int out_size)
{
    const float* x         = (const float*)d_in[0];
    const float* W_delay   = (const float*)d_in[1];
    const float* delay_raw = (const float*)d_in[2];
    const float* W_rec1    = (const float*)d_in[3];
    const float* W2        = (const float*)d_in[4];
    const float* W_rec2    = (const float*)d_in[5];
    const float* W_out     = (const float*)d_in[6];
    const float* bn1_gamma = (const float*)d_in[7];
    const float* bn1_beta  = (const float*)d_in[8];
    const float* bn1_mean  = (const float*)d_in[9];
    const float* bn1_var   = (const float*)d_in[10];
    const float* bn2_gamma = (const float*)d_in[11];
    const float* bn2_beta  = (const float*)d_in[12];
    const float* bn2_mean  = (const float*)d_in[13];
    const float* bn2_var   = (const float*)d_in[14];
    const float* alpha1    = (const float*)d_in[15];
    const float* rho1      = (const float*)d_in[16];
    const float* beta_a1   = (const float*)d_in[17];
    const float* alpha2    = (const float*)d_in[18];
    const float* rho2      = (const float*)d_in[19];
    const float* beta_a2   = (const float*)d_in[20];
    const float* beta_out  = (const float*)d_in[21];

    prep_kernel<<<(CC * H1 + 255) / 256, 256>>>(W_delay, bn1_gamma, bn1_beta, bn1_mean, bn1_var);

    xd_kernel<<<BB, 256>>>(x, delay_raw);

    dim3 gg(H1 / 128, MT / 128);   // (8, 200)
    gemm_p1_kernel<<<gg, 256>>>(alpha1);

    spec_scan_kernel<<<BB + 1, 512>>>(alpha1, rho1, beta_a1,
                                      bn2_gamma, bn2_beta, bn2_mean, bn2_var,
                                      alpha2, rho2, beta_a2,
                                      W_rec2, W_out, beta_out);

    finalize_kernel<<<BB, 512>>>(x, delay_raw, W_delay,
                                 bn1_gamma, bn1_beta, bn1_mean, bn1_var,
                                 alpha1, rho1, beta_a1,
                                 bn2_gamma, bn2_beta, bn2_mean, bn2_var,
                                 alpha2, rho2, beta_a2,
                                 W_rec1, W2, W_rec2, W_out, beta_out,
                                 (float*)d_out);
}